// round 3
// baseline (speedup 1.0000x reference)
#include <cuda_runtime.h>
#include <cuda_bf16.h>

#define N_NODES 100000

// Scratch: __device__ globals (no allocation allowed). ~2.8 MB total.
__device__ float  g_deg [N_NODES];
__device__ float  g_dinv[N_NODES];
__device__ float  g_wacc[N_NODES];   // per-src sum of dinv[dst]
__device__ float4 g_p   [N_NODES];   // propagated 4-dim features (pre-W1)
__device__ float  g_S   [64];        // sum_s w[s] * relu((p_s)W1 + b1)

// K0: re-init all state (graph replays!). deg starts at 1.0 (self loop).
__global__ void k_init() {
    int i = blockIdx.x * blockDim.x + threadIdx.x;
    if (i < N_NODES) {
        g_deg[i]  = 1.0f;
        g_wacc[i] = 0.0f;
        g_p[i]    = make_float4(0.f, 0.f, 0.f, 0.f);
    }
    if (i < 64) g_S[i] = 0.0f;
}

// K1: in-degree scatter (dst half of edge_index only). int32 indices.
__global__ void k_deg(const int* __restrict__ dst, int E) {
    int e = blockIdx.x * blockDim.x + threadIdx.x;
    if (e < E) {
        int d = dst[e];
        if ((unsigned)d < (unsigned)N_NODES)
            atomicAdd(&g_deg[d], 1.0f);
    }
}

// K2: dinv = rsqrt(deg)  (deg >= 1 always, so no zero guard needed)
__global__ void k_dinv() {
    int i = blockIdx.x * blockDim.x + threadIdx.x;
    if (i < N_NODES) g_dinv[i] = rsqrtf(g_deg[i]);
}

// K3: fused edge pass.
//   p[dst]   += x[src] * dinv[src]*dinv[dst]   (layer-1 propagation, 4-dim, vector red)
//   wacc[src] += dinv[dst]                     (layer-2+mean collapsed to scalar)
__global__ void k_edge(const int* __restrict__ src,
                       const int* __restrict__ dst,
                       const float4* __restrict__ x,
                       int E) {
    int e = blockIdx.x * blockDim.x + threadIdx.x;
    if (e >= E) return;
    int s = src[e];
    int d = dst[e];
    if ((unsigned)s >= (unsigned)N_NODES || (unsigned)d >= (unsigned)N_NODES) return;
    float ns = g_dinv[s];
    float nd = g_dinv[d];
    float norm = ns * nd;
    float4 xv = __ldg(&x[s]);
    float* pp = (float*)&g_p[d];
    asm volatile("red.global.add.v4.f32 [%0], {%1, %2, %3, %4};"
                 :: "l"(pp),
                    "f"(xv.x * norm), "f"(xv.y * norm),
                    "f"(xv.z * norm), "f"(xv.w * norm)
                 : "memory");
    atomicAdd(&g_wacc[s], nd);
}

// K4: node pass. For each node i:
//   pfull = p[i] + x[i]*dinv[i]^2            (self loop)
//   a     = relu(pfull @ W1 + b1)            (4 -> 64)
//   w     = dinv[i]*(dinv[i] + wacc[i])      (self loop + out-edge weights)
//   S    += w * a                            (64-wide weighted sum over nodes)
// Thread layout: tid&63 = output column j, tid>>6 = node subgroup (4 per block).
__global__ void k_node(const float4* __restrict__ x,
                       const float*  __restrict__ W1,
                       const float*  __restrict__ b1) {
    int j = threadIdx.x & 63;
    int g = threadIdx.x >> 6;              // 0..3
    float w0 = W1[j], w1 = W1[64 + j], w2 = W1[128 + j], w3 = W1[192 + j];
    float bb = b1[j];
    float acc = 0.f;
    for (int i = blockIdx.x * 4 + g; i < N_NODES; i += gridDim.x * 4) {
        float di    = g_dinv[i];
        float selfn = di * di;
        float4 p  = g_p[i];
        float4 xv = x[i];
        float p0 = fmaf(xv.x, selfn, p.x);
        float p1 = fmaf(xv.y, selfn, p.y);
        float p2 = fmaf(xv.z, selfn, p.z);
        float p3 = fmaf(xv.w, selfn, p.w);
        float a = fmaf(p0, w0, fmaf(p1, w1, fmaf(p2, w2, fmaf(p3, w3, bb))));
        a = fmaxf(a, 0.f);
        float wn = di * (di + g_wacc[i]);
        acc = fmaf(wn, a, acc);
    }
    __shared__ float sh[256];
    sh[threadIdx.x] = acc;
    __syncthreads();
    if (threadIdx.x < 64) {
        float s = sh[threadIdx.x] + sh[threadIdx.x + 64]
                + sh[threadIdx.x + 128] + sh[threadIdx.x + 192];
        atomicAdd(&g_S[threadIdx.x], s);
    }
}

// K5: out[k] = (S @ W2)[k] / n + b2[k]   (64x32 matvec, one warp's worth)
__global__ void k_final(const float* __restrict__ W2,
                        const float* __restrict__ b2,
                        float* __restrict__ out) {
    int k = threadIdx.x;   // 0..31
    float s = 0.f;
    #pragma unroll
    for (int j = 0; j < 64; j++) s = fmaf(g_S[j], W2[j * 32 + k], s);
    out[k] = s * (1.0f / (float)N_NODES) + b2[k];
}

extern "C" void kernel_launch(void* const* d_in, const int* in_sizes, int n_in,
                              void* d_out, int out_size) {
    const float4* x  = (const float4*)d_in[0];             // [100000, 4] f32
    const int*    ei = (const int*)d_in[1];                // [2, E] int32 (downcast from int64)
    const float*  W1 = (const float*)d_in[2];              // [4, 64]
    const float*  b1 = (const float*)d_in[3];              // [64]
    const float*  W2 = (const float*)d_in[4];              // [64, 32]
    const float*  b2 = (const float*)d_in[5];              // [32]
    float*        out = (float*)d_out;                     // [32]

    int E = in_sizes[1] / 2;
    const int* src = ei;
    const int* dst = ei + E;

    const int T = 256;
    int nb_nodes = (N_NODES + T - 1) / T;
    int nb_edges = (E + T - 1) / T;

    k_init <<<nb_nodes, T>>>();
    k_deg  <<<nb_edges, T>>>(dst, E);
    k_dinv <<<nb_nodes, T>>>();
    k_edge <<<nb_edges, T>>>(src, dst, x, E);
    k_node <<<1024, T>>>(x, W1, b1);
    k_final<<<1, 32>>>(W2, b2, out);
}